// round 2
// baseline (speedup 1.0000x reference)
#include <cuda_runtime.h>
#include <cstdint>

#define NB    2
#define NA    9
#define NHW   4096        // 64*64
#define NPROP 36864       // NHW*NA
#define NPAD  65536
#define NGRP  576         // NPROP/64
#define TOPN  2000

typedef unsigned long long u64;

// Anchors from generate_anchors(16,(0.5,1,2),(8,16,32)) with base [0,0,15,15].
__constant__ float c_anchors[9][4] = {
  { -84.f,  -40.f,  99.f,  55.f},
  {-176.f,  -88.f, 191.f, 103.f},
  {-360.f, -184.f, 375.f, 199.f},
  { -56.f,  -56.f,  71.f,  71.f},
  {-120.f, -120.f, 135.f, 135.f},
  {-248.f, -248.f, 263.f, 263.f},
  { -36.f,  -80.f,  51.f,  95.f},
  { -80.f, -168.f,  95.f, 183.f},
  {-168.f, -344.f, 183.f, 359.f}
};

__device__ float4 g_boxes [NB][NPROP];
__device__ float  g_scores[NB][NPROP];
__device__ u64    g_keys  [NB * NPAD];
__device__ float4 g_sbox  [NB][NPROP];
__device__ float  g_sscore[NB][NPROP];
__device__ float  g_sarea [NB][NPROP];
__device__ u64    g_mask  [(size_t)NB * NPROP * NGRP];   // ~340 MB scratch
__device__ int    g_keptIdx[NB][TOPN];
__device__ int    g_keptCnt[NB];

// ---------------------------------------------------------------- prep ----
__global__ __launch_bounds__(256) void k_prep(const float* __restrict__ sm,
                                              const float* __restrict__ bd,
                                              const float* __restrict__ img)
{
    int b = blockIdx.y;
    int i = blockIdx.x * 256 + threadIdx.x;       // 0..NPAD-1
    if (i >= NPAD) return;
    if (i >= NPROP) { g_keys[b * NPAD + i] = ~0ull; return; }

    int a  = i % NA;
    int hw = i / NA;
    float cx = (float)((hw & 63) * 16 + 8);
    float cy = (float)((hw >> 6) * 16 + 8);

    float ax1 = cx + c_anchors[a][0];
    float ay1 = cy + c_anchors[a][1];
    float ax2 = cx + c_anchors[a][2];
    float ay2 = cy + c_anchors[a][3];

    float wA = ax2 - ax1 + 1.0f;                  // exact small integers
    float hA = ay2 - ay1 + 1.0f;
    float ctrx = __fadd_rn(ax1, __fmul_rn(0.5f, wA));
    float ctry = __fadd_rn(ay1, __fmul_rn(0.5f, hA));

    const float* bdb = bd + ((size_t)b * 36 + (size_t)a * 4) * NHW + hw;
    float dx = bdb[0];
    float dy = bdb[NHW];
    float dw = bdb[2 * NHW];
    float dh = bdb[3 * NHW];

    // reference op order: mul then add, no contraction
    float pcx = __fadd_rn(__fmul_rn(dx, wA), ctrx);
    float pcy = __fadd_rn(__fmul_rn(dy, hA), ctry);
    float pw  = __fmul_rn(expf(dw), wA);
    float ph  = __fmul_rn(expf(dh), hA);

    float x1 = __fsub_rn(pcx, __fmul_rn(0.5f, pw));
    float y1 = __fsub_rn(pcy, __fmul_rn(0.5f, ph));
    float x2 = __fadd_rn(pcx, __fmul_rn(0.5f, pw));
    float y2 = __fadd_rn(pcy, __fmul_rn(0.5f, ph));

    float imh = img[b * 3 + 0];
    float imw = img[b * 3 + 1];
    float mx  = __fsub_rn(imw, 1.0f);
    float my  = __fsub_rn(imh, 1.0f);
    x1 = fminf(fmaxf(x1, 0.0f), mx);
    x2 = fminf(fmaxf(x2, 0.0f), mx);
    y1 = fminf(fmaxf(y1, 0.0f), my);
    y2 = fminf(fmaxf(y2, 0.0f), my);

    float s = sm[((size_t)b * 18 + 9 + a) * NHW + hw];

    g_boxes[b][i]  = make_float4(x1, y1, x2, y2);
    g_scores[b][i] = s;

    unsigned u = __float_as_uint(s);
    unsigned k = (u & 0x80000000u) ? ~u : (u | 0x80000000u);  // ascending
    unsigned kd = ~k;                                          // descending
    g_keys[b * NPAD + i] = ((u64)kd << 32) | (unsigned)i;
}

// ---------------------------------------------------------------- sort ----
// Canonical bitonic network: ascending iff ((li & len) == 0).
__global__ __launch_bounds__(1024) void k_sort_local(int startLen)
{
    __shared__ u64 sk[4096];
    int base = blockIdx.x * 4096;                 // flat over NB*NPAD
    int tid  = threadIdx.x;

#pragma unroll
    for (int e = 0; e < 4; e++) sk[e * 1024 + tid] = g_keys[base + e * 1024 + tid];
    __syncthreads();

    if (startLen == 0) {
        for (int len = 2; len <= 4096; len <<= 1) {
            for (int d = len >> 1; d > 0; d >>= 1) {
#pragma unroll
                for (int e = 0; e < 4; e++) {
                    int i = e * 1024 + tid;
                    int j = i ^ d;
                    if (j > i) {
                        int li = (base + i) & (NPAD - 1);
                        bool asc = ((li & len) == 0);
                        u64 a = sk[i], c = sk[j];
                        if ((a > c) == asc) { sk[i] = c; sk[j] = a; }
                    }
                }
                __syncthreads();
            }
        }
    } else {
        int lbase = base & (NPAD - 1);
        bool asc = ((lbase & startLen) == 0);
        for (int d = 2048; d > 0; d >>= 1) {
#pragma unroll
            for (int e = 0; e < 4; e++) {
                int i = e * 1024 + tid;
                int j = i ^ d;
                if (j > i) {
                    u64 a = sk[i], c = sk[j];
                    if ((a > c) == asc) { sk[i] = c; sk[j] = a; }
                }
            }
            __syncthreads();
        }
    }

#pragma unroll
    for (int e = 0; e < 4; e++) g_keys[base + e * 1024 + tid] = sk[e * 1024 + tid];
}

__global__ __launch_bounds__(256) void k_sort_global(int len, int d)
{
    int i = blockIdx.x * 256 + threadIdx.x;       // flat element index
    if (i >= NB * NPAD) return;
    int li = i & (NPAD - 1);
    if (li & d) return;
    int j = i + d;                                 // same batch since (li&d)==0
    bool asc = ((li & len) == 0);
    u64 a = g_keys[i], c = g_keys[j];
    if ((a > c) == asc) { g_keys[i] = c; g_keys[j] = a; }
}

// -------------------------------------------------------------- gather ----
__global__ __launch_bounds__(256) void k_gather()
{
    int b = blockIdx.y;
    int p = blockIdx.x * 256 + threadIdx.x;
    if (p >= NPROP) return;
    unsigned idx = (unsigned)(g_keys[b * NPAD + p] & 0xFFFFFFFFull);
    float4 bx = g_boxes[b][idx];
    g_sbox[b][p]   = bx;
    g_sscore[b][p] = g_scores[b][idx];
    g_sarea[b][p]  = __fmul_rn(__fadd_rn(__fsub_rn(bx.z, bx.x), 1.0f),
                               __fadd_rn(__fsub_rn(bx.w, bx.y), 1.0f));
}

// ---------------------------------------------------------------- mask ----
// Strict upper triangle: mask[i][cb] bit j = (IoU(i, cb*64+j) > 0.7), col > i.
__global__ __launch_bounds__(64) void k_mask()
{
    int cb = blockIdx.x, rb = blockIdx.y, b = blockIdx.z;
    if (cb < rb) return;

    __shared__ float4 cbx[64];
    __shared__ float  car[64];
    int t = threadIdx.x;
    cbx[t] = g_sbox[b][cb * 64 + t];
    car[t] = g_sarea[b][cb * 64 + t];
    __syncthreads();

    int i = rb * 64 + t;
    float4 bi = g_sbox[b][i];
    float  ai = g_sarea[b][i];

    u64 bits = 0;
    int js = (rb == cb) ? (t + 1) : 0;
    for (int j = js; j < 64; j++) {
        float4 bj = cbx[j];
        float iw = fmaxf(__fadd_rn(__fsub_rn(fminf(bi.z, bj.z), fmaxf(bi.x, bj.x)), 1.0f), 0.0f);
        float ih = fmaxf(__fadd_rn(__fsub_rn(fminf(bi.w, bj.w), fmaxf(bi.y, bj.y)), 1.0f), 0.0f);
        float inter = __fmul_rn(iw, ih);
        float denom = __fsub_rn(__fadd_rn(ai, car[j]), inter);
        // bracket: exact IEEE division only near the threshold
        bool sup;
        if (inter > __fmul_rn(denom, 0.700001f))      sup = true;
        else if (inter < __fmul_rn(denom, 0.699999f)) sup = false;
        else sup = (__fdiv_rn(inter, denom) > 0.7f);
        if (sup) bits |= (1ull << j);
    }
    g_mask[((size_t)b * NPROP + i) * NGRP + cb] = bits;
}

// ---------------------------------------------------------------- scan ----
__global__ __launch_bounds__(192) void k_scan()
{
    int b = blockIdx.x;
    __shared__ u64 rem[NGRP];
    __shared__ int s_c, s_kept;
    int t = threadIdx.x;
    for (int g = t; g < NGRP; g += 192) rem[g] = 0;
    if (t == 0) s_kept = 0;
    __syncthreads();

    for (int w = 0; w < NGRP; w++) {
        while (true) {
            if (t == 0) {
                u64 alive = ~rem[w];
                if (alive == 0) s_c = -1;
                else {
                    int j = __ffsll((long long)alive) - 1;
                    rem[w] |= (1ull << j);
                    int c = w * 64 + j;
                    s_c = c;
                    g_keptIdx[b][s_kept] = c;
                    s_kept++;
                }
            }
            __syncthreads();
            int c = s_c;
            if (c < 0) break;
            const u64* row = &g_mask[((size_t)b * NPROP + c) * NGRP];
            for (int g = w + t; g < NGRP; g += 192) rem[g] |= row[g];
            __syncthreads();
            if (s_kept >= TOPN) { w = NGRP; break; }
        }
    }
    __syncthreads();
    if (t == 0) g_keptCnt[b] = s_kept;
}

// ----------------------------------------------------------------- out ----
__global__ __launch_bounds__(256) void k_out(float* __restrict__ out)
{
    int idx = blockIdx.x * 256 + threadIdx.x;
    if (idx >= NB * TOPN) return;
    int b = idx / TOPN;
    int r = idx - b * TOPN;
    float* o = out + (size_t)idx * 5;
    if (r < g_keptCnt[b]) {
        int c = g_keptIdx[b][r];
        float4 bx = g_sbox[b][c];
        o[0] = g_sscore[b][c];
        o[1] = bx.x; o[2] = bx.y; o[3] = bx.z; o[4] = bx.w;
    } else {
        o[0] = 0.f; o[1] = 0.f; o[2] = 0.f; o[3] = 0.f; o[4] = 0.f;
    }
}

extern "C" void kernel_launch(void* const* d_in, const int* in_sizes, int n_in,
                              void* d_out, int out_size)
{
    const float* sm  = (const float*)d_in[0];
    const float* bd  = (const float*)d_in[1];
    const float* img = (const float*)d_in[2];
    float* out = (float*)d_out;

    k_prep<<<dim3(NPAD / 256, NB), 256>>>(sm, bd, img);

    const int nchunks = NB * NPAD / 4096;          // 32
    k_sort_local<<<nchunks, 1024>>>(0);
    for (int len = 8192; len <= NPAD; len <<= 1) {
        for (int d = len >> 1; d >= 4096; d >>= 1)
            k_sort_global<<<NB * NPAD / 256, 256>>>(len, d);
        k_sort_local<<<nchunks, 1024>>>(len);
    }

    k_gather<<<dim3(NPROP / 256, NB), 256>>>();
    k_mask<<<dim3(NGRP, NGRP, NB), 64>>>();
    k_scan<<<NB, 192>>>();
    k_out<<<(NB * TOPN + 255) / 256, 256>>>(out);
}

// round 3
// speedup vs baseline: 2.0765x; 2.0765x over previous
#include <cuda_runtime.h>
#include <cstdint>

#define NB    2
#define NA    9
#define NHW   4096        // 64*64
#define NPROP 36864       // NHW*NA
#define NPAD  65536
#define NGRP  576         // NPROP/64
#define TOPN  2000

typedef unsigned long long u64;

// Anchors from generate_anchors(16,(0.5,1,2),(8,16,32)) with base [0,0,15,15].
__constant__ float c_anchors[9][4] = {
  { -84.f,  -40.f,  99.f,  55.f},
  {-176.f,  -88.f, 191.f, 103.f},
  {-360.f, -184.f, 375.f, 199.f},
  { -56.f,  -56.f,  71.f,  71.f},
  {-120.f, -120.f, 135.f, 135.f},
  {-248.f, -248.f, 263.f, 263.f},
  { -36.f,  -80.f,  51.f,  95.f},
  { -80.f, -168.f,  95.f, 183.f},
  {-168.f, -344.f, 183.f, 359.f}
};

__device__ float4 g_boxes [NB][NPROP];
__device__ float  g_scores[NB][NPROP];
__device__ u64    g_keys  [NB * NPAD];
__device__ float4 g_sbox  [NB][NPROP];
__device__ float  g_sscore[NB][NPROP];
__device__ float  g_sarea [NB][NPROP];
// Transposed mask: g_mask[(b*NGRP + colword)*NPROP + row] — coalesced stores.
__device__ u64    g_mask  [(size_t)NB * NGRP * NPROP];
__device__ int    g_keptIdx[NB][TOPN];
__device__ int    g_keptCnt[NB];

// ---------------------------------------------------------------- prep ----
__global__ __launch_bounds__(256) void k_prep(const float* __restrict__ sm,
                                              const float* __restrict__ bd,
                                              const float* __restrict__ img)
{
    int b = blockIdx.y;
    int i = blockIdx.x * 256 + threadIdx.x;       // 0..NPAD-1
    if (i >= NPAD) return;
    if (i >= NPROP) { g_keys[b * NPAD + i] = ~0ull; return; }

    int a  = i % NA;
    int hw = i / NA;
    float cx = (float)((hw & 63) * 16 + 8);
    float cy = (float)((hw >> 6) * 16 + 8);

    float ax1 = cx + c_anchors[a][0];
    float ay1 = cy + c_anchors[a][1];
    float ax2 = cx + c_anchors[a][2];
    float ay2 = cy + c_anchors[a][3];

    float wA = ax2 - ax1 + 1.0f;                  // exact small integers
    float hA = ay2 - ay1 + 1.0f;
    float ctrx = __fadd_rn(ax1, __fmul_rn(0.5f, wA));
    float ctry = __fadd_rn(ay1, __fmul_rn(0.5f, hA));

    const float* bdb = bd + ((size_t)b * 36 + (size_t)a * 4) * NHW + hw;
    float dx = bdb[0];
    float dy = bdb[NHW];
    float dw = bdb[2 * NHW];
    float dh = bdb[3 * NHW];

    // reference op order: mul then add, no contraction
    float pcx = __fadd_rn(__fmul_rn(dx, wA), ctrx);
    float pcy = __fadd_rn(__fmul_rn(dy, hA), ctry);
    float pw  = __fmul_rn(expf(dw), wA);
    float ph  = __fmul_rn(expf(dh), hA);

    float x1 = __fsub_rn(pcx, __fmul_rn(0.5f, pw));
    float y1 = __fsub_rn(pcy, __fmul_rn(0.5f, ph));
    float x2 = __fadd_rn(pcx, __fmul_rn(0.5f, pw));
    float y2 = __fadd_rn(pcy, __fmul_rn(0.5f, ph));

    float imh = img[b * 3 + 0];
    float imw = img[b * 3 + 1];
    float mx  = __fsub_rn(imw, 1.0f);
    float my  = __fsub_rn(imh, 1.0f);
    x1 = fminf(fmaxf(x1, 0.0f), mx);
    x2 = fminf(fmaxf(x2, 0.0f), mx);
    y1 = fminf(fmaxf(y1, 0.0f), my);
    y2 = fminf(fmaxf(y2, 0.0f), my);

    float s = sm[((size_t)b * 18 + 9 + a) * NHW + hw];

    g_boxes[b][i]  = make_float4(x1, y1, x2, y2);
    g_scores[b][i] = s;

    unsigned u = __float_as_uint(s);
    unsigned k = (u & 0x80000000u) ? ~u : (u | 0x80000000u);  // ascending
    unsigned kd = ~k;                                          // descending
    g_keys[b * NPAD + i] = ((u64)kd << 32) | (unsigned)i;
}

// ---------------------------------------------------------------- sort ----
// Canonical bitonic network: ascending iff ((li & len) == 0).
__global__ __launch_bounds__(1024) void k_sort_local(int startLen)
{
    __shared__ u64 sk[4096];
    int base = blockIdx.x * 4096;                 // flat over NB*NPAD
    int tid  = threadIdx.x;

#pragma unroll
    for (int e = 0; e < 4; e++) sk[e * 1024 + tid] = g_keys[base + e * 1024 + tid];
    __syncthreads();

    if (startLen == 0) {
        for (int len = 2; len <= 4096; len <<= 1) {
            for (int d = len >> 1; d > 0; d >>= 1) {
#pragma unroll
                for (int e = 0; e < 4; e++) {
                    int i = e * 1024 + tid;
                    int j = i ^ d;
                    if (j > i) {
                        int li = (base + i) & (NPAD - 1);
                        bool asc = ((li & len) == 0);
                        u64 a = sk[i], c = sk[j];
                        if ((a > c) == asc) { sk[i] = c; sk[j] = a; }
                    }
                }
                __syncthreads();
            }
        }
    } else {
        int lbase = base & (NPAD - 1);
        bool asc = ((lbase & startLen) == 0);
        for (int d = 2048; d > 0; d >>= 1) {
#pragma unroll
            for (int e = 0; e < 4; e++) {
                int i = e * 1024 + tid;
                int j = i ^ d;
                if (j > i) {
                    u64 a = sk[i], c = sk[j];
                    if ((a > c) == asc) { sk[i] = c; sk[j] = a; }
                }
            }
            __syncthreads();
        }
    }

#pragma unroll
    for (int e = 0; e < 4; e++) g_keys[base + e * 1024 + tid] = sk[e * 1024 + tid];
}

__global__ __launch_bounds__(256) void k_sort_global(int len, int d)
{
    int i = blockIdx.x * 256 + threadIdx.x;       // flat element index
    if (i >= NB * NPAD) return;
    int li = i & (NPAD - 1);
    if (li & d) return;
    int j = i + d;                                 // same batch since (li&d)==0
    bool asc = ((li & len) == 0);
    u64 a = g_keys[i], c = g_keys[j];
    if ((a > c) == asc) { g_keys[i] = c; g_keys[j] = a; }
}

// -------------------------------------------------------------- gather ----
__global__ __launch_bounds__(256) void k_gather()
{
    int b = blockIdx.y;
    int p = blockIdx.x * 256 + threadIdx.x;
    if (p >= NPROP) return;
    unsigned idx = (unsigned)(g_keys[b * NPAD + p] & 0xFFFFFFFFull);
    float4 bx = g_boxes[b][idx];
    g_sbox[b][p]   = bx;
    g_sscore[b][p] = g_scores[b][idx];
    g_sarea[b][p]  = __fmul_rn(__fadd_rn(__fsub_rn(bx.z, bx.x), 1.0f),
                               __fadd_rn(__fsub_rn(bx.w, bx.y), 1.0f));
}

// ---------------------------------------------------------------- mask ----
// Upper triangle by 4-row-word blocks. Block = (rg, cb) with cb >= 4*rg,
// enumerated 1D: offset(rg) = 578*rg - 2*rg*rg, total 41760 per batch.
// Stores transposed: g_mask[(b*NGRP + cb)*NPROP + i].
__global__ __launch_bounds__(256) void k_mask()
{
    int b   = blockIdx.y;
    int bid = blockIdx.x;

    int rg = (int)((578.0 - sqrt(578.0 * 578.0 - 8.0 * (double)bid)) * 0.25);
    if (rg < 0) rg = 0;
    while (578 * rg - 2 * rg * rg > bid) rg--;
    while (578 * (rg + 1) - 2 * (rg + 1) * (rg + 1) <= bid) rg++;
    int cb = bid - (578 * rg - 2 * rg * rg) + 4 * rg;

    __shared__ float4 cbx[64];
    __shared__ float  car[64];
    int t = threadIdx.x;
    if (t < 64) {
        cbx[t] = g_sbox[b][cb * 64 + t];
        car[t] = g_sarea[b][cb * 64 + t];
    }
    __syncthreads();

    int rw   = 4 * rg + (t >> 6);
    int lane = t & 63;
    if (cb < rw) return;                     // strict lower: never read
    int i = rw * 64 + lane;

    float4 bi = g_sbox[b][i];
    float  ai = g_sarea[b][i];

    u64 bits = 0;
#pragma unroll 4
    for (int j = 0; j < 64; j++) {
        float4 bj = cbx[j];
        float iw = fmaxf(__fadd_rn(__fsub_rn(fminf(bi.z, bj.z), fmaxf(bi.x, bj.x)), 1.0f), 0.0f);
        float ih = fmaxf(__fadd_rn(__fsub_rn(fminf(bi.w, bj.w), fmaxf(bi.y, bj.y)), 1.0f), 0.0f);
        float inter = __fmul_rn(iw, ih);
        float s     = __fadd_rn(ai, car[j]);
        // iou > 0.7  <=>  inter > (7/17)*s  (bracketed; exact div near boundary)
        bool sup;
        if      (inter > __fmul_rn(s, 0.411775f)) sup = true;
        else if (inter < __fmul_rn(s, 0.411755f)) sup = false;
        else {
            float denom = __fsub_rn(s, inter);   // (areas_j + area_i) - inter
            sup = (__fdiv_rn(inter, denom) > 0.7f);
        }
        bits |= ((u64)sup) << j;
    }
    if (cb == rw)                            // strict upper within diagonal word
        bits &= (lane == 63) ? 0ull : (~0ull << (lane + 1));

    g_mask[((size_t)b * NGRP + cb) * NPROP + i] = bits;
}

// ---------------------------------------------------------------- scan ----
// Word-based greedy resolve: per word w, t0 resolves kept boxes serially in
// registers using prefetched diag words; then all threads OR the nk kept
// rows' words w+1.. into rem with MLP=nk. Next word's diag loads are issued
// before the resolve so their latency hides behind it.
__global__ __launch_bounds__(512) void k_scan()
{
    int b = blockIdx.x;
    int t = threadIdx.x;
    __shared__ u64 rem[NGRP];
    __shared__ u64 diag[2][64];
    __shared__ int keptL[64];
    __shared__ int s_nk, s_kept, s_done;

    for (int g = t; g < NGRP; g += 512) rem[g] = 0;
    if (t == 0) { s_kept = 0; s_done = 0; }
    if (t < 64) diag[0][t] = g_mask[((size_t)b * NGRP + 0) * NPROP + t];
    __syncthreads();

    for (int w = 0; w < NGRP; w++) {
        int par = w & 1;
        // issue next word's diag loads early (overlaps t0's serial resolve)
        u64 nd = 0;
        bool pf = (t >= 64 && t < 128 && (w + 1) < NGRP);
        if (pf)
            nd = g_mask[((size_t)b * NGRP + (w + 1)) * NPROP + ((w + 1) * 64 + (t - 64))];

        if (t == 0) {
            u64 alive = ~rem[w];
            int nk = 0, kept = s_kept;
            while (alive && kept < TOPN) {
                int j = __ffsll((long long)alive) - 1;
                int c = w * 64 + j;
                keptL[nk++] = c;
                g_keptIdx[b][kept++] = c;
                alive &= ~diag[par][j];          // in-word suppression (bits > j)
                alive &= ~(1ull << j);
            }
            s_nk = nk; s_kept = kept;
            if (kept >= TOPN) s_done = 1;
        }
        if (pf) diag[par ^ 1][t - 64] = nd;
        __syncthreads();

        if (s_done) break;
        int nk = s_nk;
        if (nk > 0) {
            for (int g = w + 1 + t; g < NGRP; g += 512) {
                u64 acc = rem[g];
                for (int i2 = 0; i2 < nk; i2++)
                    acc |= g_mask[((size_t)b * NGRP + g) * NPROP + keptL[i2]];
                rem[g] = acc;
            }
        }
        __syncthreads();
    }
    if (t == 0) g_keptCnt[b] = s_kept;
}

// ----------------------------------------------------------------- out ----
__global__ __launch_bounds__(256) void k_out(float* __restrict__ out)
{
    int idx = blockIdx.x * 256 + threadIdx.x;
    if (idx >= NB * TOPN) return;
    int b = idx / TOPN;
    int r = idx - b * TOPN;
    float* o = out + (size_t)idx * 5;
    if (r < g_keptCnt[b]) {
        int c = g_keptIdx[b][r];
        float4 bx = g_sbox[b][c];
        o[0] = g_sscore[b][c];
        o[1] = bx.x; o[2] = bx.y; o[3] = bx.z; o[4] = bx.w;
    } else {
        o[0] = 0.f; o[1] = 0.f; o[2] = 0.f; o[3] = 0.f; o[4] = 0.f;
    }
}

extern "C" void kernel_launch(void* const* d_in, const int* in_sizes, int n_in,
                              void* d_out, int out_size)
{
    const float* sm  = (const float*)d_in[0];
    const float* bd  = (const float*)d_in[1];
    const float* img = (const float*)d_in[2];
    float* out = (float*)d_out;

    k_prep<<<dim3(NPAD / 256, NB), 256>>>(sm, bd, img);

    const int nchunks = NB * NPAD / 4096;          // 32
    k_sort_local<<<nchunks, 1024>>>(0);
    for (int len = 8192; len <= NPAD; len <<= 1) {
        for (int d = len >> 1; d >= 4096; d >>= 1)
            k_sort_global<<<NB * NPAD / 256, 256>>>(len, d);
        k_sort_local<<<nchunks, 1024>>>(len);
    }

    k_gather<<<dim3(NPROP / 256, NB), 256>>>();
    k_mask<<<dim3(41760, NB), 256>>>();
    k_scan<<<NB, 512>>>();
    k_out<<<(NB * TOPN + 255) / 256, 256>>>(out);
}

// round 4
// speedup vs baseline: 2.1450x; 1.0330x over previous
#include <cuda_runtime.h>
#include <cstdint>

#define NB    2
#define NA    9
#define NHW   4096        // 64*64
#define NPROP 36864       // NHW*NA
#define NPAD  65536
#define NGRP  576         // NPROP/64
#define TOPN  2000
#define CH    8           // words per scan chunk
#define NCH   (NGRP/CH)   // 72
#define RWB   16          // row-words per mask block
#define NBLK  10656       // sum_{k<36}(576-16k)

typedef unsigned long long u64;

// Anchors from generate_anchors(16,(0.5,1,2),(8,16,32)) with base [0,0,15,15].
__constant__ float c_anchors[9][4] = {
  { -84.f,  -40.f,  99.f,  55.f},
  {-176.f,  -88.f, 191.f, 103.f},
  {-360.f, -184.f, 375.f, 199.f},
  { -56.f,  -56.f,  71.f,  71.f},
  {-120.f, -120.f, 135.f, 135.f},
  {-248.f, -248.f, 263.f, 263.f},
  { -36.f,  -80.f,  51.f,  95.f},
  { -80.f, -168.f,  95.f, 183.f},
  {-168.f, -344.f, 183.f, 359.f}
};

__device__ float4 g_boxes [NB][NPROP];
__device__ float  g_scores[NB][NPROP];
__device__ u64    g_keys  [NB * NPAD];
__device__ float4 g_sbox  [NB][NPROP];
__device__ float  g_sscore[NB][NPROP];
__device__ float  g_sarea [NB][NPROP];
// Transposed mask: g_mask[(b*NGRP + colword)*NPROP + row] — coalesced.
// Zero-initialized at module load; lower triangle never written, never used.
__device__ u64    g_mask  [(size_t)NB * NGRP * NPROP];
__device__ int    g_keptIdx[NB][TOPN];
__device__ int    g_keptCnt[NB];

// ---------------------------------------------------------------- prep ----
__global__ __launch_bounds__(256) void k_prep(const float* __restrict__ sm,
                                              const float* __restrict__ bd,
                                              const float* __restrict__ img)
{
    int b = blockIdx.y;
    int i = blockIdx.x * 256 + threadIdx.x;       // 0..NPAD-1
    if (i >= NPAD) return;
    if (i >= NPROP) { g_keys[b * NPAD + i] = ~0ull; return; }

    int a  = i % NA;
    int hw = i / NA;
    float cx = (float)((hw & 63) * 16 + 8);
    float cy = (float)((hw >> 6) * 16 + 8);

    float ax1 = cx + c_anchors[a][0];
    float ay1 = cy + c_anchors[a][1];
    float ax2 = cx + c_anchors[a][2];
    float ay2 = cy + c_anchors[a][3];

    float wA = ax2 - ax1 + 1.0f;                  // exact small integers
    float hA = ay2 - ay1 + 1.0f;
    float ctrx = __fadd_rn(ax1, __fmul_rn(0.5f, wA));
    float ctry = __fadd_rn(ay1, __fmul_rn(0.5f, hA));

    const float* bdb = bd + ((size_t)b * 36 + (size_t)a * 4) * NHW + hw;
    float dx = bdb[0];
    float dy = bdb[NHW];
    float dw = bdb[2 * NHW];
    float dh = bdb[3 * NHW];

    // reference op order: mul then add, no contraction
    float pcx = __fadd_rn(__fmul_rn(dx, wA), ctrx);
    float pcy = __fadd_rn(__fmul_rn(dy, hA), ctry);
    float pw  = __fmul_rn(expf(dw), wA);
    float ph  = __fmul_rn(expf(dh), hA);

    float x1 = __fsub_rn(pcx, __fmul_rn(0.5f, pw));
    float y1 = __fsub_rn(pcy, __fmul_rn(0.5f, ph));
    float x2 = __fadd_rn(pcx, __fmul_rn(0.5f, pw));
    float y2 = __fadd_rn(pcy, __fmul_rn(0.5f, ph));

    float imh = img[b * 3 + 0];
    float imw = img[b * 3 + 1];
    float mx  = __fsub_rn(imw, 1.0f);
    float my  = __fsub_rn(imh, 1.0f);
    x1 = fminf(fmaxf(x1, 0.0f), mx);
    x2 = fminf(fmaxf(x2, 0.0f), mx);
    y1 = fminf(fmaxf(y1, 0.0f), my);
    y2 = fminf(fmaxf(y2, 0.0f), my);

    float s = sm[((size_t)b * 18 + 9 + a) * NHW + hw];

    g_boxes[b][i]  = make_float4(x1, y1, x2, y2);
    g_scores[b][i] = s;

    unsigned u = __float_as_uint(s);
    unsigned k = (u & 0x80000000u) ? ~u : (u | 0x80000000u);  // ascending
    unsigned kd = ~k;                                          // descending
    g_keys[b * NPAD + i] = ((u64)kd << 32) | (unsigned)i;
}

// ---------------------------------------------------------------- sort ----
// 16384-element chunks in 128KB dynamic smem. Canonical bitonic:
// ascending iff ((li & len) == 0).
__global__ __launch_bounds__(1024) void k_sort_local(int startLen)
{
    extern __shared__ u64 sk[];
    int base = blockIdx.x * 16384;                // flat over NB*NPAD
    int tid  = threadIdx.x;

#pragma unroll
    for (int e = 0; e < 16; e++) sk[e * 1024 + tid] = g_keys[base + e * 1024 + tid];
    __syncthreads();

    if (startLen == 0) {
        for (int len = 2; len <= 16384; len <<= 1) {
            for (int d = len >> 1; d > 0; d >>= 1) {
#pragma unroll
                for (int e = 0; e < 8; e++) {
                    int idx = e * 1024 + tid;          // 0..8191 pair ids
                    int i = ((idx & ~(d - 1)) << 1) | (idx & (d - 1));
                    int j = i | d;
                    int li = (base + i) & (NPAD - 1);
                    bool asc = ((li & len) == 0);
                    u64 a = sk[i], c = sk[j];
                    if ((a > c) == asc) { sk[i] = c; sk[j] = a; }
                }
                __syncthreads();
            }
        }
    } else {
        bool asc = (((base & (NPAD - 1)) & startLen) == 0);
        for (int d = 8192; d > 0; d >>= 1) {
#pragma unroll
            for (int e = 0; e < 8; e++) {
                int idx = e * 1024 + tid;
                int i = ((idx & ~(d - 1)) << 1) | (idx & (d - 1));
                int j = i | d;
                u64 a = sk[i], c = sk[j];
                if ((a > c) == asc) { sk[i] = c; sk[j] = a; }
            }
            __syncthreads();
        }
    }

#pragma unroll
    for (int e = 0; e < 16; e++) g_keys[base + e * 1024 + tid] = sk[e * 1024 + tid];
}

__global__ __launch_bounds__(256) void k_sort_global(int len, int d)
{
    int i = blockIdx.x * 256 + threadIdx.x;       // flat element index
    if (i >= NB * NPAD) return;
    int li = i & (NPAD - 1);
    if (li & d) return;
    int j = i + d;                                 // same batch since (li&d)==0
    bool asc = ((li & len) == 0);
    u64 a = g_keys[i], c = g_keys[j];
    if ((a > c) == asc) { g_keys[i] = c; g_keys[j] = a; }
}

// -------------------------------------------------------------- gather ----
__global__ __launch_bounds__(256) void k_gather()
{
    int b = blockIdx.y;
    int p = blockIdx.x * 256 + threadIdx.x;
    if (p >= NPROP) return;
    unsigned idx = (unsigned)(g_keys[b * NPAD + p] & 0xFFFFFFFFull);
    float4 bx = g_boxes[b][idx];
    g_sbox[b][p]   = bx;
    g_sscore[b][p] = g_scores[b][idx];
    g_sarea[b][p]  = __fmul_rn(__fadd_rn(__fsub_rn(bx.z, bx.x), 1.0f),
                               __fadd_rn(__fsub_rn(bx.w, bx.y), 1.0f));
}

// ---------------------------------------------------------------- mask ----
// Block = (rg of 16 row-words, col word cb >= 16*rg), 1D triangular grid.
// offset(rg) = 584*rg - 8*rg^2. 256 threads, 4 rows/thread.
// Stores transposed: g_mask[(b*NGRP + cb)*NPROP + i], upper triangle only.
__global__ __launch_bounds__(256) void k_mask()
{
    int b   = blockIdx.y;
    int bid = blockIdx.x;

    int rg = (int)((584.0 - sqrt(584.0 * 584.0 - 32.0 * (double)bid)) / 16.0);
    if (rg < 0) rg = 0;
    while (584 * rg - 8 * rg * rg > bid) rg--;
    while (584 * (rg + 1) - 8 * (rg + 1) * (rg + 1) <= bid) rg++;
    int cb = bid - (584 * rg - 8 * rg * rg) + RWB * rg;

    __shared__ float4 cbx[64];
    __shared__ float  car[64];
    int t = threadIdx.x;
    if (t < 64) {
        cbx[t] = g_sbox[b][cb * 64 + t];
        car[t] = g_sarea[b][cb * 64 + t];
    }
    __syncthreads();

    int base = rg * (RWB * 64);                   // 1024*rg
    float4 bi[4]; float ai[4]; u64 bits[4];
#pragma unroll
    for (int e = 0; e < 4; e++) {
        int i = base + e * 256 + t;
        bi[e] = g_sbox[b][i];
        ai[e] = g_sarea[b][i];
        bits[e] = 0;
    }

#pragma unroll 8
    for (int j = 0; j < 64; j++) {
        float4 bj = cbx[j];
        float  aj = car[j];
#pragma unroll
        for (int e = 0; e < 4; e++) {
            float iw = fmaxf(__fadd_rn(__fsub_rn(fminf(bi[e].z, bj.z), fmaxf(bi[e].x, bj.x)), 1.0f), 0.0f);
            float ih = fmaxf(__fadd_rn(__fsub_rn(fminf(bi[e].w, bj.w), fmaxf(bi[e].y, bj.y)), 1.0f), 0.0f);
            float inter = __fmul_rn(iw, ih);
            float s     = __fadd_rn(ai[e], aj);
            // iou > 0.7  <=>  inter > (7/17)*s  (bracketed; exact div near edge)
            bool sup;
            if      (inter > __fmul_rn(s, 0.411775f)) sup = true;
            else if (inter < __fmul_rn(s, 0.411755f)) sup = false;
            else sup = (__fdiv_rn(inter, __fsub_rn(s, inter)) > 0.7f);
            bits[e] |= ((u64)sup) << j;
        }
    }

#pragma unroll
    for (int e = 0; e < 4; e++) {
        int i  = base + e * 256 + t;
        int rw = i >> 6;
        if (cb < rw) continue;                    // strict lower: never used
        u64 v = bits[e];
        if (cb == rw) {                           // strict upper within diag word
            int lane = i & 63;
            v &= (lane == 63) ? 0ull : (~0ull << (lane + 1));
        }
        g_mask[((size_t)b * NGRP + cb) * NPROP + i] = v;
    }
}

// ---------------------------------------------------------------- scan ----
// Chunked greedy resolve: per 8-word chunk, preload the 512x8 mask block into
// smem (coalesced), resolve the 8 words entirely out of smem (no global
// latency in the serial chain), then batch-propagate the chunk's kept rows
// into rem[] for all later words with high MLP.
__global__ __launch_bounds__(512) void k_scan()
{
    int b = blockIdx.x;
    int t = threadIdx.x;
    __shared__ u64 rem[NGRP];        // suppression bits per word
    __shared__ u64 blk[CH][512];     // chunk-local mask block (32KB)
    __shared__ int ckept[512];       // kept local-row ids within chunk
    __shared__ int s_kept, s_done, s_nk, s_nkc;

    for (int g = t; g < NGRP; g += 512) rem[g] = 0;
    if (t == 0) { s_kept = 0; s_done = 0; }
    __syncthreads();

    const size_t mb = (size_t)b * NGRP;
    for (int c = 0; c < NCH; c++) {
        int W0 = c * CH;
        int R0 = W0 * 64;
#pragma unroll
        for (int w = 0; w < CH; w++)
            blk[w][t] = g_mask[(mb + W0 + w) * NPROP + R0 + t];
        if (t == 0) s_nkc = 0;
        __syncthreads();

        for (int wl = 0; wl < CH; wl++) {
            if (t == 0) {
                u64 alive = ~rem[W0 + wl];
                int nk = 0, kept = s_kept, nkc = s_nkc;
                while (alive && kept < TOPN) {
                    int j = __ffsll((long long)alive) - 1;
                    g_keptIdx[b][kept++] = (W0 + wl) * 64 + j;
                    int lr = wl * 64 + j;
                    ckept[nkc++] = lr;
                    nk++;
                    alive &= ~blk[wl][lr];        // in-word suppression
                    alive &= ~(1ull << j);
                }
                s_nk = nk; s_kept = kept; s_nkc = nkc;
                if (kept >= TOPN) s_done = 1;
            }
            __syncthreads();
            if (s_done) break;
            int nk = s_nk;
            if (nk > 0 && t < CH - 1 - wl) {       // OR into later chunk words
                int w2 = wl + 1 + t;
                u64 acc = rem[W0 + w2];
                int q0 = s_nkc - nk;
                for (int q = q0; q < s_nkc; q++) acc |= blk[w2][ckept[q]];
                rem[W0 + w2] = acc;
            }
            __syncthreads();
        }
        if (s_done) break;

        int nkc = s_nkc;                           // propagate to later words
        if (nkc > 0) {
            for (int g = W0 + CH + t; g < NGRP; g += 512) {
                u64 acc = rem[g];
                const u64* row = &g_mask[(mb + g) * NPROP + R0];
                for (int q = 0; q < nkc; q++) acc |= row[ckept[q]];
                rem[g] = acc;
            }
        }
        __syncthreads();
    }
    if (t == 0) g_keptCnt[b] = s_kept;
}

// ----------------------------------------------------------------- out ----
__global__ __launch_bounds__(256) void k_out(float* __restrict__ out)
{
    int idx = blockIdx.x * 256 + threadIdx.x;
    if (idx >= NB * TOPN) return;
    int b = idx / TOPN;
    int r = idx - b * TOPN;
    float* o = out + (size_t)idx * 5;
    if (r < g_keptCnt[b]) {
        int c = g_keptIdx[b][r];
        float4 bx = g_sbox[b][c];
        o[0] = g_sscore[b][c];
        o[1] = bx.x; o[2] = bx.y; o[3] = bx.z; o[4] = bx.w;
    } else {
        o[0] = 0.f; o[1] = 0.f; o[2] = 0.f; o[3] = 0.f; o[4] = 0.f;
    }
}

extern "C" void kernel_launch(void* const* d_in, const int* in_sizes, int n_in,
                              void* d_out, int out_size)
{
    const float* sm  = (const float*)d_in[0];
    const float* bd  = (const float*)d_in[1];
    const float* img = (const float*)d_in[2];
    float* out = (float*)d_out;

    cudaFuncSetAttribute(k_sort_local,
                         cudaFuncAttributeMaxDynamicSharedMemorySize, 131072);

    k_prep<<<dim3(NPAD / 256, NB), 256>>>(sm, bd, img);

    const int nchunks = NB * NPAD / 16384;         // 8
    const size_t smem = 131072;
    k_sort_local<<<nchunks, 1024, smem>>>(0);
    k_sort_global<<<NB * NPAD / 256, 256>>>(32768, 16384);
    k_sort_local<<<nchunks, 1024, smem>>>(32768);
    k_sort_global<<<NB * NPAD / 256, 256>>>(65536, 32768);
    k_sort_global<<<NB * NPAD / 256, 256>>>(65536, 16384);
    k_sort_local<<<nchunks, 1024, smem>>>(65536);

    k_gather<<<dim3(NPROP / 256, NB), 256>>>();
    k_mask<<<dim3(NBLK, NB), 256>>>();
    k_scan<<<NB, 512>>>();
    k_out<<<(NB * TOPN + 255) / 256, 256>>>(out);
}

// round 5
// speedup vs baseline: 3.0276x; 1.4115x over previous
#include <cuda_runtime.h>
#include <cstdint>

#define NB    2
#define NA    9
#define NHW   4096        // 64*64
#define NPROP 36864       // NHW*NA
#define NPAD  65536
#define NGRP  576         // NPROP/64
#define TOPN  2000
#define CH    8           // words per scan chunk
#define NCH   (NGRP/CH)   // 72
#define RWB   16          // row-words per mask block
#define CHA   16          // phase-A chunks (rows 0..8191)
#define RGA   8           // phase-A row-groups (words 0..127)
#define NBLKA 4160        // sum_{rg<8}(576-16rg)
#define NBLKB 6496        // sum_{rg=8..35}(576-16rg)

typedef unsigned long long u64;

// Anchors from generate_anchors(16,(0.5,1,2),(8,16,32)) with base [0,0,15,15].
__constant__ float c_anchors[9][4] = {
  { -84.f,  -40.f,  99.f,  55.f},
  {-176.f,  -88.f, 191.f, 103.f},
  {-360.f, -184.f, 375.f, 199.f},
  { -56.f,  -56.f,  71.f,  71.f},
  {-120.f, -120.f, 135.f, 135.f},
  {-248.f, -248.f, 263.f, 263.f},
  { -36.f,  -80.f,  51.f,  95.f},
  { -80.f, -168.f,  95.f, 183.f},
  {-168.f, -344.f, 183.f, 359.f}
};

__device__ float4 g_boxes [NB][NPROP];
__device__ float  g_scores[NB][NPROP];
__device__ u64    g_keys  [NB * NPAD];
__device__ float4 g_sbox  [NB][NPROP];
__device__ float  g_sscore[NB][NPROP];
__device__ float  g_sarea [NB][NPROP];
// Transposed mask: g_mask[(b*NGRP + colword)*NPROP + row] — coalesced.
__device__ u64    g_mask  [(size_t)NB * NGRP * NPROP];
__device__ u64    g_rem   [NB][NGRP];
__device__ int    g_keptIdx[NB][TOPN];
__device__ int    g_keptCnt[NB];
__device__ int    g_done  [NB];

// ---------------------------------------------------------------- prep ----
__global__ __launch_bounds__(256) void k_prep(const float* __restrict__ sm,
                                              const float* __restrict__ bd,
                                              const float* __restrict__ img)
{
    int b = blockIdx.y;
    int i = blockIdx.x * 256 + threadIdx.x;       // 0..NPAD-1
    if (i == 0) g_done[b] = 0;                    // reset per launch
    if (i >= NPAD) return;
    if (i >= NPROP) { g_keys[b * NPAD + i] = ~0ull; return; }

    int a  = i % NA;
    int hw = i / NA;
    float cx = (float)((hw & 63) * 16 + 8);
    float cy = (float)((hw >> 6) * 16 + 8);

    float ax1 = cx + c_anchors[a][0];
    float ay1 = cy + c_anchors[a][1];
    float ax2 = cx + c_anchors[a][2];
    float ay2 = cy + c_anchors[a][3];

    float wA = ax2 - ax1 + 1.0f;                  // exact small integers
    float hA = ay2 - ay1 + 1.0f;
    float ctrx = __fadd_rn(ax1, __fmul_rn(0.5f, wA));
    float ctry = __fadd_rn(ay1, __fmul_rn(0.5f, hA));

    const float* bdb = bd + ((size_t)b * 36 + (size_t)a * 4) * NHW + hw;
    float dx = bdb[0];
    float dy = bdb[NHW];
    float dw = bdb[2 * NHW];
    float dh = bdb[3 * NHW];

    // reference op order: mul then add, no contraction
    float pcx = __fadd_rn(__fmul_rn(dx, wA), ctrx);
    float pcy = __fadd_rn(__fmul_rn(dy, hA), ctry);
    float pw  = __fmul_rn(expf(dw), wA);
    float ph  = __fmul_rn(expf(dh), hA);

    float x1 = __fsub_rn(pcx, __fmul_rn(0.5f, pw));
    float y1 = __fsub_rn(pcy, __fmul_rn(0.5f, ph));
    float x2 = __fadd_rn(pcx, __fmul_rn(0.5f, pw));
    float y2 = __fadd_rn(pcy, __fmul_rn(0.5f, ph));

    float imh = img[b * 3 + 0];
    float imw = img[b * 3 + 1];
    float mx  = __fsub_rn(imw, 1.0f);
    float my  = __fsub_rn(imh, 1.0f);
    x1 = fminf(fmaxf(x1, 0.0f), mx);
    x2 = fminf(fmaxf(x2, 0.0f), mx);
    y1 = fminf(fmaxf(y1, 0.0f), my);
    y2 = fminf(fmaxf(y2, 0.0f), my);

    float s = sm[((size_t)b * 18 + 9 + a) * NHW + hw];

    g_boxes[b][i]  = make_float4(x1, y1, x2, y2);
    g_scores[b][i] = s;

    unsigned u = __float_as_uint(s);
    unsigned k = (u & 0x80000000u) ? ~u : (u | 0x80000000u);  // ascending
    unsigned kd = ~k;                                          // descending
    g_keys[b * NPAD + i] = ((u64)kd << 32) | (unsigned)i;
}

// ---------------------------------------------------------------- sort ----
// 16384-element chunks in 128KB dynamic smem. Canonical bitonic:
// ascending iff ((li & len) == 0).
__global__ __launch_bounds__(1024) void k_sort_local(int startLen)
{
    extern __shared__ u64 sk[];
    int base = blockIdx.x * 16384;                // flat over NB*NPAD
    int tid  = threadIdx.x;

#pragma unroll
    for (int e = 0; e < 16; e++) sk[e * 1024 + tid] = g_keys[base + e * 1024 + tid];
    __syncthreads();

    if (startLen == 0) {
        for (int len = 2; len <= 16384; len <<= 1) {
            for (int d = len >> 1; d > 0; d >>= 1) {
#pragma unroll
                for (int e = 0; e < 8; e++) {
                    int idx = e * 1024 + tid;          // 0..8191 pair ids
                    int i = ((idx & ~(d - 1)) << 1) | (idx & (d - 1));
                    int j = i | d;
                    int li = (base + i) & (NPAD - 1);
                    bool asc = ((li & len) == 0);
                    u64 a = sk[i], c = sk[j];
                    if ((a > c) == asc) { sk[i] = c; sk[j] = a; }
                }
                __syncthreads();
            }
        }
    } else {
        bool asc = (((base & (NPAD - 1)) & startLen) == 0);
        for (int d = 8192; d > 0; d >>= 1) {
#pragma unroll
            for (int e = 0; e < 8; e++) {
                int idx = e * 1024 + tid;
                int i = ((idx & ~(d - 1)) << 1) | (idx & (d - 1));
                int j = i | d;
                u64 a = sk[i], c = sk[j];
                if ((a > c) == asc) { sk[i] = c; sk[j] = a; }
            }
            __syncthreads();
        }
    }

#pragma unroll
    for (int e = 0; e < 16; e++) g_keys[base + e * 1024 + tid] = sk[e * 1024 + tid];
}

__global__ __launch_bounds__(256) void k_sort_global(int len, int d)
{
    int i = blockIdx.x * 256 + threadIdx.x;       // flat element index
    if (i >= NB * NPAD) return;
    int li = i & (NPAD - 1);
    if (li & d) return;
    int j = i + d;                                 // same batch since (li&d)==0
    bool asc = ((li & len) == 0);
    u64 a = g_keys[i], c = g_keys[j];
    if ((a > c) == asc) { g_keys[i] = c; g_keys[j] = a; }
}

// -------------------------------------------------------------- gather ----
__global__ __launch_bounds__(256) void k_gather()
{
    int b = blockIdx.y;
    int p = blockIdx.x * 256 + threadIdx.x;
    if (p >= NPROP) return;
    unsigned idx = (unsigned)(g_keys[b * NPAD + p] & 0xFFFFFFFFull);
    float4 bx = g_boxes[b][idx];
    g_sbox[b][p]   = bx;
    g_sscore[b][p] = g_scores[b][idx];
    g_sarea[b][p]  = __fmul_rn(__fadd_rn(__fsub_rn(bx.z, bx.x), 1.0f),
                               __fadd_rn(__fsub_rn(bx.w, bx.y), 1.0f));
}

// ---------------------------------------------------------------- mask ----
// Block = (rg of 16 row-words, col word cb >= 16*rg), 1D triangular grid with
// global offset(rg) = 584*rg - 8*rg^2. Phase A: bids [0,NBLKA); phase B:
// bids [NBLKA, NBLKA+NBLKB) via bidOffset, early-exits when g_done is set.
// Branch-free hot loop: definite-suppress + ambiguous bitmasks; ambiguous
// bits (rare) resolved post-loop with the exact reference-order division.
__global__ __launch_bounds__(256) void k_mask(int bidOffset, int checkFlag)
{
    int b = blockIdx.y;
    if (checkFlag && g_done[b]) return;
    int bid = blockIdx.x + bidOffset;

    int rg = (int)((584.0 - sqrt(584.0 * 584.0 - 32.0 * (double)bid)) / 16.0);
    if (rg < 0) rg = 0;
    while (584 * rg - 8 * rg * rg > bid) rg--;
    while (584 * (rg + 1) - 8 * (rg + 1) * (rg + 1) <= bid) rg++;
    int cb = bid - (584 * rg - 8 * rg * rg) + RWB * rg;

    __shared__ float4 cbx[64];
    __shared__ float  car[64];
    int t = threadIdx.x;
    if (t < 64) {
        cbx[t] = g_sbox[b][cb * 64 + t];
        car[t] = g_sarea[b][cb * 64 + t];
    }
    __syncthreads();

    int base = rg * (RWB * 64);                   // 1024*rg
    float4 bi[4]; float ai[4]; u64 bsup[4]; u64 bamb[4];
#pragma unroll
    for (int e = 0; e < 4; e++) {
        int i = base + e * 256 + t;
        bi[e] = g_sbox[b][i];
        ai[e] = g_sarea[b][i];
        bsup[e] = 0; bamb[e] = 0;
    }

#pragma unroll 8
    for (int j = 0; j < 64; j++) {
        float4 bj = cbx[j];
        float  aj = car[j];
#pragma unroll
        for (int e = 0; e < 4; e++) {
            float iw = fmaxf(__fadd_rn(__fsub_rn(fminf(bi[e].z, bj.z), fmaxf(bi[e].x, bj.x)), 1.0f), 0.0f);
            float ih = fmaxf(__fadd_rn(__fsub_rn(fminf(bi[e].w, bj.w), fmaxf(bi[e].y, bj.y)), 1.0f), 0.0f);
            float inter = __fmul_rn(iw, ih);
            float s     = __fadd_rn(ai[e], aj);
            // iou > 0.7  <=>  inter > (7/17)*s ; band resolved exactly below
            bool hi = inter > __fmul_rn(s, 0.411775f);
            bool lo = inter < __fmul_rn(s, 0.411755f);
            bsup[e] |= ((u64)hi) << j;
            bamb[e] |= ((u64)(!hi && !lo)) << j;
        }
    }

    // rare exact resolution (identical op order to reference)
#pragma unroll
    for (int e = 0; e < 4; e++) {
        u64 am = bamb[e];
        while (am) {
            int j = __ffsll((long long)am) - 1;
            am &= am - 1;
            float4 bj = cbx[j];
            float iw = fmaxf(__fadd_rn(__fsub_rn(fminf(bi[e].z, bj.z), fmaxf(bi[e].x, bj.x)), 1.0f), 0.0f);
            float ih = fmaxf(__fadd_rn(__fsub_rn(fminf(bi[e].w, bj.w), fmaxf(bi[e].y, bj.y)), 1.0f), 0.0f);
            float inter = __fmul_rn(iw, ih);
            float s     = __fadd_rn(ai[e], car[j]);
            float denom = __fsub_rn(s, inter);
            if (__fdiv_rn(inter, denom) > 0.7f) bsup[e] |= (1ull << j);
        }
    }

#pragma unroll
    for (int e = 0; e < 4; e++) {
        int i  = base + e * 256 + t;
        int rw = i >> 6;
        if (cb < rw) continue;                    // strict lower: never used
        u64 v = bsup[e];
        if (cb == rw) {                           // strict upper within diag word
            int lane = i & 63;
            v &= (lane == 63) ? 0ull : (~0ull << (lane + 1));
        }
        g_mask[((size_t)b * NGRP + cb) * NPROP + i] = v;
    }
}

// ---------------------------------------------------------------- scan ----
// Chunked greedy resolve over chunks [c0, c1). Phase A (c0==0) initializes
// state; phase B resumes from g_rem / g_keptCnt and early-exits when done.
__global__ __launch_bounds__(512) void k_scan(int c0, int c1)
{
    int b = blockIdx.x;
    if (c0 > 0 && g_done[b]) return;
    int t = threadIdx.x;
    __shared__ u64 rem[NGRP];        // suppression bits per word
    __shared__ u64 blk[CH][512];     // chunk-local mask block (32KB)
    __shared__ int ckept[512];       // kept local-row ids within chunk
    __shared__ int s_kept, s_done, s_nk, s_nkc;

    if (c0 == 0) {
        for (int g = t; g < NGRP; g += 512) rem[g] = 0;
        if (t == 0) { s_kept = 0; s_done = 0; }
    } else {
        for (int g = t; g < NGRP; g += 512) rem[g] = g_rem[b][g];
        if (t == 0) { s_kept = g_keptCnt[b]; s_done = 0; }
    }
    __syncthreads();

    const size_t mb = (size_t)b * NGRP;
    for (int c = c0; c < c1; c++) {
        int W0 = c * CH;
        int R0 = W0 * 64;
#pragma unroll
        for (int w = 0; w < CH; w++)
            blk[w][t] = g_mask[(mb + W0 + w) * NPROP + R0 + t];
        if (t == 0) s_nkc = 0;
        __syncthreads();

        for (int wl = 0; wl < CH; wl++) {
            if (t == 0) {
                u64 alive = ~rem[W0 + wl];
                int nk = 0, kept = s_kept, nkc = s_nkc;
                while (alive && kept < TOPN) {
                    int j = __ffsll((long long)alive) - 1;
                    g_keptIdx[b][kept++] = (W0 + wl) * 64 + j;
                    int lr = wl * 64 + j;
                    ckept[nkc++] = lr;
                    nk++;
                    alive &= ~blk[wl][lr];        // in-word suppression
                    alive &= ~(1ull << j);
                }
                s_nk = nk; s_kept = kept; s_nkc = nkc;
                if (kept >= TOPN) s_done = 1;
            }
            __syncthreads();
            if (s_done) break;
            int nk = s_nk;
            if (nk > 0 && t < CH - 1 - wl) {       // OR into later chunk words
                int w2 = wl + 1 + t;
                u64 acc = rem[W0 + w2];
                int q0 = s_nkc - nk;
                for (int q = q0; q < s_nkc; q++) acc |= blk[w2][ckept[q]];
                rem[W0 + w2] = acc;
            }
            __syncthreads();
        }
        if (s_done) break;

        int nkc = s_nkc;                           // propagate to later words
        if (nkc > 0) {
            for (int g = W0 + CH + t; g < NGRP; g += 512) {
                u64 acc = rem[g];
                const u64* row = &g_mask[(mb + g) * NPROP + R0];
                for (int q = 0; q < nkc; q++) acc |= row[ckept[q]];
                rem[g] = acc;
            }
        }
        __syncthreads();
    }

    if (s_done) {
        if (t == 0) { g_done[b] = 1; g_keptCnt[b] = s_kept; }
    } else {
        for (int g = t; g < NGRP; g += 512) g_rem[b][g] = rem[g];
        if (t == 0) g_keptCnt[b] = s_kept;   // running count (final if c1==NCH)
    }
}

// ----------------------------------------------------------------- out ----
__global__ __launch_bounds__(256) void k_out(float* __restrict__ out)
{
    int idx = blockIdx.x * 256 + threadIdx.x;
    if (idx >= NB * TOPN) return;
    int b = idx / TOPN;
    int r = idx - b * TOPN;
    float* o = out + (size_t)idx * 5;
    if (r < g_keptCnt[b]) {
        int c = g_keptIdx[b][r];
        float4 bx = g_sbox[b][c];
        o[0] = g_sscore[b][c];
        o[1] = bx.x; o[2] = bx.y; o[3] = bx.z; o[4] = bx.w;
    } else {
        o[0] = 0.f; o[1] = 0.f; o[2] = 0.f; o[3] = 0.f; o[4] = 0.f;
    }
}

extern "C" void kernel_launch(void* const* d_in, const int* in_sizes, int n_in,
                              void* d_out, int out_size)
{
    const float* sm  = (const float*)d_in[0];
    const float* bd  = (const float*)d_in[1];
    const float* img = (const float*)d_in[2];
    float* out = (float*)d_out;

    cudaFuncSetAttribute(k_sort_local,
                         cudaFuncAttributeMaxDynamicSharedMemorySize, 131072);

    k_prep<<<dim3(NPAD / 256, NB), 256>>>(sm, bd, img);

    const int nchunks = NB * NPAD / 16384;         // 8
    const size_t smem = 131072;
    k_sort_local<<<nchunks, 1024, smem>>>(0);
    k_sort_global<<<NB * NPAD / 256, 256>>>(32768, 16384);
    k_sort_local<<<nchunks, 1024, smem>>>(32768);
    k_sort_global<<<NB * NPAD / 256, 256>>>(65536, 32768);
    k_sort_global<<<NB * NPAD / 256, 256>>>(65536, 16384);
    k_sort_local<<<nchunks, 1024, smem>>>(65536);

    k_gather<<<dim3(NPROP / 256, NB), 256>>>();

    // Phase A: mask rows 0..8191, scan chunks 0..15 (sets g_done if TOPN hit)
    k_mask<<<dim3(NBLKA, NB), 256>>>(0, 0);
    k_scan<<<NB, 512>>>(0, CHA);
    // Phase B: remainder; early-exits when phase A finished
    k_mask<<<dim3(NBLKB, NB), 256>>>(NBLKA, 1);
    k_scan<<<NB, 512>>>(CHA, NCH);

    k_out<<<(NB * TOPN + 255) / 256, 256>>>(out);
}

// round 6
// speedup vs baseline: 9.1599x; 3.0255x over previous
#include <cuda_runtime.h>
#include <cstdint>

#define NB    2
#define NA    9
#define NHW   4096        // 64*64
#define NPROP 36864       // NHW*NA
#define NPAD  65536
#define TOPN  2000
#define WIN   1024        // candidates per window
#define WRD   16          // 64-bit words per window
#define NWIN  36          // WIN*NWIN = NPROP

typedef unsigned long long u64;

// Anchors from generate_anchors(16,(0.5,1,2),(8,16,32)) with base [0,0,15,15].
__constant__ float c_anchors[9][4] = {
  { -84.f,  -40.f,  99.f,  55.f},
  {-176.f,  -88.f, 191.f, 103.f},
  {-360.f, -184.f, 375.f, 199.f},
  { -56.f,  -56.f,  71.f,  71.f},
  {-120.f, -120.f, 135.f, 135.f},
  {-248.f, -248.f, 263.f, 263.f},
  { -36.f,  -80.f,  51.f,  95.f},
  { -80.f, -168.f,  95.f, 183.f},
  {-168.f, -344.f, 183.f, 359.f}
};

__device__ float4 g_boxes [NB][NPROP];
__device__ float  g_scores[NB][NPROP];
__device__ u64    g_keys  [NB * NPAD];
__device__ float4 g_sbox  [NB][NPROP];
__device__ float  g_sscore[NB][NPROP];
__device__ float  g_sarea [NB][NPROP];
__device__ u64    g_wmask [NB][WRD][WIN];   // current window mask, [word][row]
__device__ u64    g_remw  [NB][WRD];        // kept-box suppression for window
__device__ float4 g_kbox  [NB][TOPN];       // kept boxes (for later mask phases)
__device__ float  g_karea [NB][TOPN];
__device__ int    g_keptIdx[NB][TOPN];
__device__ int    g_keptCnt[NB];
__device__ int    g_done  [NB];

// ---------------------------------------------------------------- prep ----
__global__ __launch_bounds__(256) void k_prep(const float* __restrict__ sm,
                                              const float* __restrict__ bd,
                                              const float* __restrict__ img)
{
    int b = blockIdx.y;
    int i = blockIdx.x * 256 + threadIdx.x;       // 0..NPAD-1
    if (i == 0) { g_done[b] = 0; g_keptCnt[b] = 0; }
    if (i < WRD) g_remw[b][i] = 0;
    if (i >= NPAD) return;
    if (i >= NPROP) { g_keys[b * NPAD + i] = ~0ull; return; }

    int a  = i % NA;
    int hw = i / NA;
    float cx = (float)((hw & 63) * 16 + 8);
    float cy = (float)((hw >> 6) * 16 + 8);

    float ax1 = cx + c_anchors[a][0];
    float ay1 = cy + c_anchors[a][1];
    float ax2 = cx + c_anchors[a][2];
    float ay2 = cy + c_anchors[a][3];

    float wA = ax2 - ax1 + 1.0f;                  // exact small integers
    float hA = ay2 - ay1 + 1.0f;
    float ctrx = __fadd_rn(ax1, __fmul_rn(0.5f, wA));
    float ctry = __fadd_rn(ay1, __fmul_rn(0.5f, hA));

    const float* bdb = bd + ((size_t)b * 36 + (size_t)a * 4) * NHW + hw;
    float dx = bdb[0];
    float dy = bdb[NHW];
    float dw = bdb[2 * NHW];
    float dh = bdb[3 * NHW];

    // reference op order: mul then add, no contraction
    float pcx = __fadd_rn(__fmul_rn(dx, wA), ctrx);
    float pcy = __fadd_rn(__fmul_rn(dy, hA), ctry);
    float pw  = __fmul_rn(expf(dw), wA);
    float ph  = __fmul_rn(expf(dh), hA);

    float x1 = __fsub_rn(pcx, __fmul_rn(0.5f, pw));
    float y1 = __fsub_rn(pcy, __fmul_rn(0.5f, ph));
    float x2 = __fadd_rn(pcx, __fmul_rn(0.5f, pw));
    float y2 = __fadd_rn(pcy, __fmul_rn(0.5f, ph));

    float imh = img[b * 3 + 0];
    float imw = img[b * 3 + 1];
    float mx  = __fsub_rn(imw, 1.0f);
    float my  = __fsub_rn(imh, 1.0f);
    x1 = fminf(fmaxf(x1, 0.0f), mx);
    x2 = fminf(fmaxf(x2, 0.0f), mx);
    y1 = fminf(fmaxf(y1, 0.0f), my);
    y2 = fminf(fmaxf(y2, 0.0f), my);

    float s = sm[((size_t)b * 18 + 9 + a) * NHW + hw];

    g_boxes[b][i]  = make_float4(x1, y1, x2, y2);
    g_scores[b][i] = s;

    unsigned u = __float_as_uint(s);
    unsigned k = (u & 0x80000000u) ? ~u : (u | 0x80000000u);  // ascending
    unsigned kd = ~k;                                          // descending
    g_keys[b * NPAD + i] = ((u64)kd << 32) | (unsigned)i;
}

// ---------------------------------------------------------------- sort ----
// 16384-element chunks in 128KB dynamic smem. Canonical bitonic:
// ascending iff ((li & len) == 0).
__global__ __launch_bounds__(1024) void k_sort_local(int startLen)
{
    extern __shared__ u64 sk[];
    int base = blockIdx.x * 16384;                // flat over NB*NPAD
    int tid  = threadIdx.x;

#pragma unroll
    for (int e = 0; e < 16; e++) sk[e * 1024 + tid] = g_keys[base + e * 1024 + tid];
    __syncthreads();

    if (startLen == 0) {
        for (int len = 2; len <= 16384; len <<= 1) {
            for (int d = len >> 1; d > 0; d >>= 1) {
#pragma unroll
                for (int e = 0; e < 8; e++) {
                    int idx = e * 1024 + tid;          // 0..8191 pair ids
                    int i = ((idx & ~(d - 1)) << 1) | (idx & (d - 1));
                    int j = i | d;
                    int li = (base + i) & (NPAD - 1);
                    bool asc = ((li & len) == 0);
                    u64 a = sk[i], c = sk[j];
                    if ((a > c) == asc) { sk[i] = c; sk[j] = a; }
                }
                __syncthreads();
            }
        }
    } else {
        bool asc = (((base & (NPAD - 1)) & startLen) == 0);
        for (int d = 8192; d > 0; d >>= 1) {
#pragma unroll
            for (int e = 0; e < 8; e++) {
                int idx = e * 1024 + tid;
                int i = ((idx & ~(d - 1)) << 1) | (idx & (d - 1));
                int j = i | d;
                u64 a = sk[i], c = sk[j];
                if ((a > c) == asc) { sk[i] = c; sk[j] = a; }
            }
            __syncthreads();
        }
    }

#pragma unroll
    for (int e = 0; e < 16; e++) g_keys[base + e * 1024 + tid] = sk[e * 1024 + tid];
}

__global__ __launch_bounds__(256) void k_sort_global(int len, int d)
{
    int i = blockIdx.x * 256 + threadIdx.x;       // flat element index
    if (i >= NB * NPAD) return;
    int li = i & (NPAD - 1);
    if (li & d) return;
    int j = i + d;                                 // same batch since (li&d)==0
    bool asc = ((li & len) == 0);
    u64 a = g_keys[i], c = g_keys[j];
    if ((a > c) == asc) { g_keys[i] = c; g_keys[j] = a; }
}

// -------------------------------------------------------------- gather ----
__global__ __launch_bounds__(256) void k_gather()
{
    int b = blockIdx.y;
    int p = blockIdx.x * 256 + threadIdx.x;
    if (p >= NPROP) return;
    unsigned idx = (unsigned)(g_keys[b * NPAD + p] & 0xFFFFFFFFull);
    float4 bx = g_boxes[b][idx];
    g_sbox[b][p]   = bx;
    g_sscore[b][p] = g_scores[b][idx];
    g_sarea[b][p]  = __fmul_rn(__fadd_rn(__fsub_rn(bx.z, bx.x), 1.0f),
                               __fadd_rn(__fsub_rn(bx.w, bx.y), 1.0f));
}

// --------------------------------------------------------- window mask ----
// Phase k: blocks 0..15 compute the 1024x1024 in-window mask rows (stored
// [word][row] for the scan's coalesced load); blocks 16..47 compute bits of
// previously-kept boxes vs the window's columns and OR them into g_remw.
// Branch-free hot loop; ambiguous IoU band resolved exactly post-loop.
__global__ __launch_bounds__(512) void k_maskw(int k)
{
    int b = blockIdx.y;
    if (g_done[b]) return;
    int bx = blockIdx.x;
    int keptCnt = g_keptCnt[b];
    if (bx >= 16 && (bx - 16) * 64 >= keptCnt) return;

    int t    = threadIdx.x;
    int rl   = t & 63;                 // row within 64-row group
    int cg   = t >> 6;                 // 0..7, each handles 2 words
    int R0   = k * WIN;

    __shared__ float4 cbx[WIN];
    __shared__ float  car[WIN];
    for (int j = t; j < WIN; j += 512) {
        cbx[j] = g_sbox[b][R0 + j];
        car[j] = g_sarea[b][R0 + j];
    }
    __shared__ u64 red[8][2];
    if (t < 16) ((u64*)red)[t] = 0;
    __syncthreads();

    float4 bi; float ai; bool active = true;
    if (bx < 16) {
        int i = R0 + bx * 64 + rl;
        bi = g_sbox[b][i];
        ai = g_sarea[b][i];
    } else {
        int kr = (bx - 16) * 64 + rl;
        active = (kr < keptCnt);
        if (active) { bi = g_kbox[b][kr]; ai = g_karea[b][kr]; }
    }

    u64 res[2];
#pragma unroll
    for (int ww = 0; ww < 2; ww++) {
        int w = cg * 2 + ww;
        int wb = w * 64;
        u64 bsup = 0, bamb = 0;
        if (active) {
#pragma unroll 8
            for (int j2 = 0; j2 < 64; j2++) {
                float4 bj = cbx[wb + j2];
                float  aj = car[wb + j2];
                float iw = fmaxf(__fadd_rn(__fsub_rn(fminf(bi.z, bj.z), fmaxf(bi.x, bj.x)), 1.0f), 0.0f);
                float ih = fmaxf(__fadd_rn(__fsub_rn(fminf(bi.w, bj.w), fmaxf(bi.y, bj.y)), 1.0f), 0.0f);
                float inter = __fmul_rn(iw, ih);
                float s     = __fadd_rn(ai, aj);
                bool hi = inter > __fmul_rn(s, 0.411775f);
                bool lo = inter < __fmul_rn(s, 0.411755f);
                bsup |= ((u64)hi) << j2;
                bamb |= ((u64)(!hi && !lo)) << j2;
            }
            while (bamb) {                         // rare exact resolution
                int j2 = __ffsll((long long)bamb) - 1;
                bamb &= bamb - 1;
                float4 bj = cbx[wb + j2];
                float iw = fmaxf(__fadd_rn(__fsub_rn(fminf(bi.z, bj.z), fmaxf(bi.x, bj.x)), 1.0f), 0.0f);
                float ih = fmaxf(__fadd_rn(__fsub_rn(fminf(bi.w, bj.w), fmaxf(bi.y, bj.y)), 1.0f), 0.0f);
                float inter = __fmul_rn(iw, ih);
                float s     = __fadd_rn(ai, car[wb + j2]);
                float denom = __fsub_rn(s, inter);
                if (__fdiv_rn(inter, denom) > 0.7f) bsup |= (1ull << j2);
            }
        }
        res[ww] = bsup;
    }

    if (bx < 16) {
        // strict-upper within own word (self + earlier lanes cleared)
#pragma unroll
        for (int ww = 0; ww < 2; ww++) {
            int w = cg * 2 + ww;
            u64 v = res[ww];
            if (w == bx) v &= (rl == 63) ? 0ull : (~0ull << (rl + 1));
            g_wmask[b][w][bx * 64 + rl] = v;
        }
    } else {
        if (active) {
            atomicOr(&red[cg][0], res[0]);
            atomicOr(&red[cg][1], res[1]);
        }
        __syncthreads();
        if (rl < 2) {
            u64 v = red[cg][rl];
            if (v) atomicOr(&g_remw[b][cg * 2 + rl], v);
        }
    }
}

// --------------------------------------------------------- window scan ----
// One block per batch. Loads the full 128KB window mask into smem, seeds rem
// with the kept-box contributions, and resolves all 16 words in shared memory
// (word-batched greedy). Appends newly-kept boxes for later mask phases.
__global__ __launch_bounds__(512) void k_scanw(int k)
{
    int b = blockIdx.x;
    if (g_done[b]) return;
    int t = threadIdx.x;
    extern __shared__ u64 blk[];                  // [WRD][WIN]
    __shared__ u64 rem[WRD];
    __shared__ short ckeptL[WIN];
    __shared__ int s_kept, s_nk, s_nkc, s_done;

    const ulonglong2* src = (const ulonglong2*)&g_wmask[b][0][0];
    ulonglong2* dst = (ulonglong2*)blk;
#pragma unroll
    for (int q = 0; q < WRD; q++) dst[q * 512 + t] = src[q * 512 + t];
    if (t < WRD) rem[t] = g_remw[b][t];
    if (t == 0) { s_kept = g_keptCnt[b]; s_done = 0; s_nkc = 0; }
    __syncthreads();

    for (int wl = 0; wl < WRD; wl++) {
        if (t == 0) {
            u64 alive = ~rem[wl];
            int nk = 0, kept = s_kept, nkc = s_nkc;
            while (alive && kept < TOPN) {
                int j = __ffsll((long long)alive) - 1;
                int lr = wl * 64 + j;
                g_keptIdx[b][kept++] = k * WIN + lr;
                ckeptL[nkc++] = (short)lr;
                nk++;
                alive &= ~blk[wl * WIN + lr];     // in-word suppression
                alive &= ~(1ull << j);
            }
            s_nk = nk; s_kept = kept; s_nkc = nkc;
            if (kept >= TOPN) s_done = 1;
        }
        __syncthreads();
        if (s_done) break;
        int nk = s_nk;
        if (nk > 0 && t < WRD - 1 - wl) {
            int w2 = wl + 1 + t;
            u64 acc = rem[w2];
            int q0 = s_nkc - nk;
            for (int q = q0; q < s_nkc; q++) acc |= blk[w2 * WIN + ckeptL[q]];
            rem[w2] = acc;
        }
        __syncthreads();
    }

    // epilogue: publish kept boxes for future mask phases
    int nkc = s_nkc;
    int kept0 = g_keptCnt[b];
    for (int q = t; q < nkc; q += 512) {
        int c = k * WIN + ckeptL[q];
        g_kbox[b][kept0 + q]  = g_sbox[b][c];
        g_karea[b][kept0 + q] = g_sarea[b][c];
    }
    if (t == 0) {
        g_keptCnt[b] = s_kept;
        if (s_done) g_done[b] = 1;
    }
    if (t < WRD) g_remw[b][t] = 0;                // reset for next phase
}

// ----------------------------------------------------------------- out ----
__global__ __launch_bounds__(256) void k_out(float* __restrict__ out)
{
    int idx = blockIdx.x * 256 + threadIdx.x;
    if (idx >= NB * TOPN) return;
    int b = idx / TOPN;
    int r = idx - b * TOPN;
    float* o = out + (size_t)idx * 5;
    if (r < g_keptCnt[b]) {
        int c = g_keptIdx[b][r];
        float4 bx = g_sbox[b][c];
        o[0] = g_sscore[b][c];
        o[1] = bx.x; o[2] = bx.y; o[3] = bx.z; o[4] = bx.w;
    } else {
        o[0] = 0.f; o[1] = 0.f; o[2] = 0.f; o[3] = 0.f; o[4] = 0.f;
    }
}

extern "C" void kernel_launch(void* const* d_in, const int* in_sizes, int n_in,
                              void* d_out, int out_size)
{
    const float* sm  = (const float*)d_in[0];
    const float* bd  = (const float*)d_in[1];
    const float* img = (const float*)d_in[2];
    float* out = (float*)d_out;

    cudaFuncSetAttribute(k_sort_local,
                         cudaFuncAttributeMaxDynamicSharedMemorySize, 131072);
    cudaFuncSetAttribute(k_scanw,
                         cudaFuncAttributeMaxDynamicSharedMemorySize, 131072);

    k_prep<<<dim3(NPAD / 256, NB), 256>>>(sm, bd, img);

    const int nchunks = NB * NPAD / 16384;         // 8
    const size_t ssm = 131072;
    k_sort_local<<<nchunks, 1024, ssm>>>(0);
    k_sort_global<<<NB * NPAD / 256, 256>>>(32768, 16384);
    k_sort_local<<<nchunks, 1024, ssm>>>(32768);
    k_sort_global<<<NB * NPAD / 256, 256>>>(65536, 32768);
    k_sort_global<<<NB * NPAD / 256, 256>>>(65536, 16384);
    k_sort_local<<<nchunks, 1024, ssm>>>(65536);

    k_gather<<<dim3(NPROP / 256, NB), 256>>>();

    for (int k = 0; k < NWIN; k++) {
        k_maskw<<<dim3(48, NB), 512>>>(k);
        k_scanw<<<NB, 512, 131072>>>(k);
    }

    k_out<<<(NB * TOPN + 255) / 256, 256>>>(out);
}